// round 6
// baseline (speedup 1.0000x reference)
#include <cuda_runtime.h>
#include <cuda_bf16.h>

// DMN_Encoder: 3-hop memory network, B=128, N=2048, D=128.
// Two-kernel pipeline:
//  K1 (grid B*8, 256thr): per 256-row slice -> ballot compaction, stream
//     active fp32 rows once, compute hop-invariant s=v·w_f, write segment-
//     compacted bf16 copy, and fuse the full hop-0 accumulation (cb0 needs
//     only e1). Emits per-slice partial (o,l) sums.
//  K2 (grid B, 1024thr): reduce hop-0 partials -> u1, then hops 1-2 over the
//     compact bf16 scratch (fits in L2), single exp per active row per hop.

#define B_ 128
#define N_ 2048
#define D_ 128
#define SLICES 8
#define SROWS (N_ / SLICES)          // 256 rows per slice

__device__ uint2  g_vbf[(size_t)B_ * N_ * (D_ / 4)];   // 67MB bf16 scratch (segmented compact)
__device__ float  g_s[(size_t)B_ * N_];                // hop-invariant s, compact
__device__ float  g_part[(size_t)B_ * SLICES * 132];   // per-slice partials: o[128], l at [128]
__device__ int    g_cnt[(size_t)B_ * SLICES];          // per-slice active count

// ============================ K1 ============================
__global__ __launch_bounds__(256, 4)
void dmn_k1(const float* __restrict__ e1,
            const float* __restrict__ value,
            const float* __restrict__ mask,
            const float* __restrict__ attw,
            const float* __restrict__ attb)
{
    const int blk  = blockIdx.x;
    const int b    = blk >> 3;
    const int sl   = blk & 7;
    const int tid  = threadIdx.x;
    const int lane = tid & 31;
    const int warp = tid >> 5;           // 0..7

    __shared__ unsigned short tmp_s[SROWS];
    __shared__ unsigned short dense_s[SROWS];
    __shared__ int cntw_s[8], offw_s[8], tot_s;
    __shared__ __align__(16) float acc_s[8][D_];
    __shared__ float lpart_s[8];

    const float4* attw4 = reinterpret_cast<const float4*>(attw);
    const float4 wf4 = attw4[lane];
    const float4 wu4 = attw4[32 + lane];

    // ---- ballot compaction of this slice's active rows ----
    {
        const float m = mask[(size_t)b * N_ + sl * SROWS + warp * 32 + lane];
        const unsigned bal = __ballot_sync(0xffffffffu, m != 0.f);
        if (m != 0.f)
            tmp_s[warp * 32 + __popc(bal & ((1u << lane) - 1u))]
                = (unsigned short)(warp * 32 + lane);
        if (lane == 0) cntw_s[warp] = __popc(bal);
    }
    __syncthreads();
    if (tid == 0) {
        int o = 0;
        #pragma unroll
        for (int i = 0; i < 8; i++) { offw_s[i] = o; o += cntw_s[i]; }
        tot_s = o;
    }
    __syncthreads();
    for (int j = lane; j < cntw_s[warp]; j += 32)
        dense_s[offw_s[warp] + j] = tmp_s[warp * 32 + j];

    // ---- cb0 = e1·w_u + b0 (redundant per warp) ----
    const float4 e4 = reinterpret_cast<const float4*>(e1 + (size_t)b * D_)[lane];
    float cp = e4.x*wu4.x + e4.y*wu4.y + e4.z*wu4.z + e4.w*wu4.w;
    #pragma unroll
    for (int o = 16; o; o >>= 1) cp += __shfl_xor_sync(0xffffffffu, cp, o);
    const float cb    = cp + attb[0];
    const float sigma = fmaxf(cb, 0.f);
    __syncthreads();

    const int cnt = tot_s;
    const int kb  = (cnt * warp) >> 3;
    const int ke  = (cnt * (warp + 1)) >> 3;

    const float* vb = value + (size_t)b * N_ * D_;
    float a0 = 0.f, a1 = 0.f, a2 = 0.f, a3 = 0.f, l = 0.f;

    #pragma unroll 4
    for (int k = kb; k < ke; k++) {
        const int n  = sl * SROWS + dense_s[k];       // row within batch
        const int kp = sl * SROWS + k;                // compact output position
        const float4 v4 = reinterpret_cast<const float4*>(vb + (size_t)n * D_)[lane];
        float s = v4.x*wf4.x + v4.y*wf4.y + v4.z*wf4.z + v4.w*wf4.w;
        #pragma unroll
        for (int o = 16; o; o >>= 1) s += __shfl_xor_sync(0xffffffffu, s, o);
        if (lane == 0) g_s[(size_t)b * N_ + kp] = s;
        __nv_bfloat162 p0 = __floats2bfloat162_rn(v4.x, v4.y);
        __nv_bfloat162 p1 = __floats2bfloat162_rn(v4.z, v4.w);
        uint2 pk;
        pk.x = *reinterpret_cast<unsigned int*>(&p0);
        pk.y = *reinterpret_cast<unsigned int*>(&p1);
        g_vbf[((size_t)b * N_ + kp) * 32 + lane] = pk;
        const float att = fmaxf(s + cb, 0.f);
        const float w   = __expf(fminf(att - sigma, 80.f));
        l += w;
        a0 = fmaf(w, v4.x, a0);
        a1 = fmaf(w, v4.y, a1);
        a2 = fmaf(w, v4.z, a2);
        a3 = fmaf(w, v4.w, a3);
    }

    reinterpret_cast<float4*>(&acc_s[warp][lane * 4])[0] = make_float4(a0, a1, a2, a3);
    if (lane == 0) lpart_s[warp] = l;          // l is warp-uniform
    __syncthreads();

    float* part = g_part + ((size_t)b * SLICES + sl) * 132;
    if (tid < D_) {
        float o = 0.f;
        #pragma unroll
        for (int w = 0; w < 8; w++) o += acc_s[w][tid];
        part[tid] = o;
    } else if (tid == D_) {
        float lt = 0.f;
        #pragma unroll
        for (int w = 0; w < 8; w++) lt += lpart_s[w];
        part[D_] = lt;
    } else if (tid == D_ + 1) {
        g_cnt[b * SLICES + sl] = cnt;
    }
}

// ============================ K2 ============================
__global__ __launch_bounds__(1024, 1)
void dmn_k2(const float* __restrict__ e1,
            const float* __restrict__ linw,
            const float* __restrict__ linb,
            const float* __restrict__ attw,
            const float* __restrict__ attb,
            float* __restrict__ out)
{
    const int b    = blockIdx.x;
    const int tid  = threadIdx.x;
    const int lane = tid & 31;
    const int warp = tid >> 5;           // 0..31

    __shared__ float s_c[N_];            // 8KB
    __shared__ float w_c[N_];            // 8KB
    __shared__ unsigned short dense2[N_]; // 4KB (segment positions)
    __shared__ __align__(16) float u_s[D_];
    __shared__ __align__(16) float ub_s[D_];
    __shared__ __align__(16) float acc8[8][D_];   // 4KB phased accumulator
    __shared__ float l_s[32];
    __shared__ int cnt8[8], po8[8], tot_s;

    const float4* attw4 = reinterpret_cast<const float4*>(attw);
    const float4 wf_unused = attw4[lane]; (void)wf_unused;
    const float4 wu4 = attw4[32 + lane];
    const float  b0  = attb[0];

    if (tid < 8) cnt8[tid] = g_cnt[b * SLICES + tid];
    __syncthreads();
    if (tid == 0) {
        int o = 0;
        #pragma unroll
        for (int i = 0; i < 8; i++) { po8[i] = o; o += cnt8[i]; }
        tot_s = o;
    }
    __syncthreads();
    if (warp < 8)
        for (int j = lane; j < cnt8[warp]; j += 32)
            dense2[po8[warp] + j] = (unsigned short)(warp * SROWS + j);
    __syncthreads();
    const int total = tot_s;

    // gather compact s into smem
    for (int j = tid; j < total; j += 1024)
        s_c[j] = g_s[(size_t)b * N_ + dense2[j]];

    // ---- u1 = relu(e1@W^T+lb) + o0/l0 ----
    const float4 e4 = reinterpret_cast<const float4*>(e1 + (size_t)b * D_)[lane];
    #pragma unroll
    for (int r = 0; r < 4; r++) {
        const int i = warp * 4 + r;
        const float4 w4 = reinterpret_cast<const float4*>(linw + (size_t)i * D_)[lane];
        float p = w4.x*e4.x + w4.y*e4.y + w4.z*e4.z + w4.w*e4.w;
        #pragma unroll
        for (int o = 16; o; o >>= 1) p += __shfl_xor_sync(0xffffffffu, p, o);
        if (lane == 0) ub_s[i] = fmaxf(p + linb[i], 0.f);
    }
    __syncthreads();
    if (tid < D_) {
        const float* part = g_part + (size_t)b * SLICES * 132;
        float oa = 0.f, lt = 1e-5f;
        #pragma unroll
        for (int sl = 0; sl < 8; sl++) {
            oa += part[sl * 132 + tid];
            lt += part[sl * 132 + D_];
        }
        u_s[tid] = ub_s[tid] + oa / lt;
    }
    __syncthreads();

    const uint2* vbf = g_vbf + (size_t)b * N_ * 32;

    // ---- hops 1 and 2 ----
    #pragma unroll 1
    for (int hop = 0; hop < 2; hop++) {
        const float4 u4 = reinterpret_cast<const float4*>(u_s)[lane];
        float cp = u4.x*wu4.x + u4.y*wu4.y + u4.z*wu4.z + u4.w*wu4.w;
        #pragma unroll
        for (int o = 16; o; o >>= 1) cp += __shfl_xor_sync(0xffffffffu, cp, o);
        const float cb    = cp + b0;
        const float sigma = fmaxf(cb, 0.f);

        #pragma unroll
        for (int r = 0; r < 4; r++) {
            const int i = warp * 4 + r;
            const float4 w4 = reinterpret_cast<const float4*>(linw + (size_t)i * D_)[lane];
            float p = w4.x*u4.x + w4.y*u4.y + w4.z*u4.z + w4.w*u4.w;
            #pragma unroll
            for (int o = 16; o; o >>= 1) p += __shfl_xor_sync(0xffffffffu, p, o);
            if (lane == 0) ub_s[i] = fmaxf(p + linb[i], 0.f);
        }

        // weight sweep: one exp per active row + fused l partials
        float lsum = 0.f;
        for (int k = tid; k < total; k += 1024) {
            const float att = fmaxf(s_c[k] + cb, 0.f);
            const float w   = __expf(fminf(att - sigma, 80.f));
            w_c[k] = w;
            lsum += w;
        }
        #pragma unroll
        for (int o = 16; o; o >>= 1) lsum += __shfl_xor_sync(0xffffffffu, lsum, o);
        if (lane == 0) l_s[warp] = lsum;
        __syncthreads();

        // bf16 stream over compact rows (L2-resident scratch)
        const int kb = (total * warp) >> 5;
        const int ke = (total * (warp + 1)) >> 5;
        float a0 = 0.f, a1 = 0.f, a2 = 0.f, a3 = 0.f;
        #pragma unroll 8
        for (int k = kb; k < ke; k++) {
            const int pos = dense2[k];
            const uint2 pk = vbf[(size_t)pos * 32 + lane];
            const float w  = w_c[k];
            const float2 f0 = __bfloat1622float2(*reinterpret_cast<const __nv_bfloat162*>(&pk.x));
            const float2 f1 = __bfloat1622float2(*reinterpret_cast<const __nv_bfloat162*>(&pk.y));
            a0 = fmaf(w, f0.x, a0);
            a1 = fmaf(w, f0.y, a1);
            a2 = fmaf(w, f1.x, a2);
            a3 = fmaf(w, f1.y, a3);
        }

        // phased cross-warp accumulation into acc8[8][128]
        #pragma unroll 1
        for (int g = 0; g < 4; g++) {
            __syncthreads();
            if ((warp >> 3) == g) {
                float* dst = acc8[warp & 7] + lane * 4;
                if (g == 0) {
                    dst[0] = a0; dst[1] = a1; dst[2] = a2; dst[3] = a3;
                } else {
                    dst[0] += a0; dst[1] += a1; dst[2] += a2; dst[3] += a3;
                }
            }
        }
        __syncthreads();

        if (tid < D_) {
            float lt = 1e-5f;
            #pragma unroll
            for (int w = 0; w < 32; w++) lt += l_s[w];
            float oa = 0.f;
            #pragma unroll
            for (int j = 0; j < 8; j++) oa += acc8[j][tid];
            u_s[tid] = ub_s[tid] + oa / lt;
        }
        __syncthreads();
    }

    if (tid < D_) out[(size_t)b * D_ + tid] = u_s[tid];
}

extern "C" void kernel_launch(void* const* d_in, const int* in_sizes, int n_in,
                              void* d_out, int out_size)
{
    // 0 e1, 1 rel(unused), 2 key(unused), 3 value, 4 mask,
    // 5 linfc_w, 6 linfc_b, 7 attfc_w, 8 attfc_b, 9 dim(unused)
    const float* e1    = (const float*)d_in[0];
    const float* value = (const float*)d_in[3];
    const float* nmask = (const float*)d_in[4];
    const float* linw  = (const float*)d_in[5];
    const float* linb  = (const float*)d_in[6];
    const float* attw  = (const float*)d_in[7];
    const float* attb  = (const float*)d_in[8];
    (void)in_sizes; (void)n_in; (void)out_size;

    dmn_k1<<<B_ * SLICES, 256>>>(e1, value, nmask, attw, attb);
    dmn_k2<<<B_, 1024>>>(e1, linw, linb, attw, attb, (float*)d_out);
}